// round 9
// baseline (speedup 1.0000x reference)
#include <cuda_runtime.h>
#include <cuda_fp16.h>
#include <mma.h>
#include <math.h>
#include <stdint.h>

using namespace nvcuda;

#define TOK  2048
#define HDIM 2048
#define FDIM 7168
#define NEXP 8
#define TOPK 2

#define BM 128
#define BN 128
#define BK 64
#define NC1 (HDIM / BK)   // 32
#define NC2 (FDIM / BK)   // 112

#define ALDH 72           // A smem row stride (halves): 64 data + 8 pad = 144B
#define BLDH 136          // B smem row stride (halves): 128 data + 8 pad = 272B
#define CLD  136          // epilogue float stride

#define ASZH (BM * ALDH)          // 9216 halves
#define BSZH (BK * BLDH)          // 8704 halves
#define STG1H (ASZH + 2 * BSZH)   // 26624 halves = 53248 B
#define STG2H (ASZH + BSZH)       // 17920 halves = 35840 B
#define DYN1 (2 * STG1H * 2)      // 106496 B (2-stage)
#define DYN2 (3 * STG2H * 2)      // 107520 B (3-stage)

// ---------------- scratch ----------------
__device__ int    g_cnt[NEXP];
__device__ int    g_tok[NEXP * TOK];
__device__ int    g_dst[NEXP * TOK];
__device__ float  g_wt [NEXP * TOK];
__device__ __half g_xh  [(size_t)TOK * HDIM];
__device__ __half g_w1h [(size_t)NEXP * HDIM * FDIM];
__device__ __half g_w3h [(size_t)NEXP * HDIM * FDIM];
__device__ __half g_w2h [(size_t)NEXP * FDIM * HDIM];
__device__ __half g_hidh[(size_t)NEXP * TOK * FDIM];
__device__ float  g_partial[(size_t)TOK * TOPK * HDIM];

// ---------------- helpers ----------------
__device__ __forceinline__ uint32_t smem_u32(const void* p) {
    uint32_t a;
    asm("{ .reg .u64 t; cvta.to.shared.u64 t, %1; cvt.u32.u64 %0, t; }" : "=r"(a) : "l"(p));
    return a;
}
__device__ __forceinline__ void cpa(uint32_t s, const void* g) {
    asm volatile("cp.async.cg.shared.global [%0], [%1], 16;" :: "r"(s), "l"(g));
}
__device__ __forceinline__ void cpcommit() { asm volatile("cp.async.commit_group;"); }
template <int N>
__device__ __forceinline__ void cpwait() { asm volatile("cp.async.wait_group %0;" :: "n"(N)); }

// ---------------- small kernels ----------------
__global__ void zero_kernel() {
    if (threadIdx.x < NEXP) g_cnt[threadIdx.x] = 0;
}

// fp32 gate: exact top-2 matches jax.lax.top_k (strict > keeps lowest index on ties)
__global__ void route_kernel(const float* __restrict__ x, const float* __restrict__ gw) {
    const int t   = blockIdx.x;
    const int tid = threadIdx.x;

    float acc[NEXP];
#pragma unroll
    for (int e = 0; e < NEXP; e++) acc[e] = 0.f;

    const float* xt = x + (size_t)t * HDIM;
    for (int h = tid; h < HDIM; h += 256) {
        float xv = xt[h];
#pragma unroll
        for (int e = 0; e < NEXP; e++) acc[e] += xv * gw[h * NEXP + e];
    }

    __shared__ float s[NEXP][256];
#pragma unroll
    for (int e = 0; e < NEXP; e++) s[e][tid] = acc[e];
    __syncthreads();
    for (int off = 128; off > 0; off >>= 1) {
        if (tid < off) {
#pragma unroll
            for (int e = 0; e < NEXP; e++) s[e][tid] += s[e][tid + off];
        }
        __syncthreads();
    }

    if (tid == 0) {
        float v[NEXP];
#pragma unroll
        for (int e = 0; e < NEXP; e++) v[e] = s[e][0];
        int i1 = 0;
#pragma unroll
        for (int e = 1; e < NEXP; e++) if (v[e] > v[i1]) i1 = e;
        int i2 = (i1 == 0) ? 1 : 0;
#pragma unroll
        for (int e = 0; e < NEXP; e++)
            if (e != i1 && v[e] > v[i2]) i2 = e;

        float m  = fmaxf(v[i1], v[i2]);
        float e1 = __expf(v[i1] - m);
        float e2 = __expf(v[i2] - m);
        float inv = 1.f / (e1 + e2);

        int s0 = atomicAdd(&g_cnt[i1], 1);
        g_tok[i1 * TOK + s0] = t;
        g_dst[i1 * TOK + s0] = t * TOPK + 0;
        g_wt [i1 * TOK + s0] = e1 * inv;
        int s1 = atomicAdd(&g_cnt[i2], 1);
        g_tok[i2 * TOK + s1] = t;
        g_dst[i2 * TOK + s1] = t * TOPK + 1;
        g_wt [i2 * TOK + s1] = e2 * inv;
    }
}

// fp32 -> fp16 (RN), 8 elems/thread
__global__ void f2h_kernel(const float* __restrict__ s, __half* __restrict__ d) {
    const size_t i = ((size_t)blockIdx.x * 256 + threadIdx.x) * 8;
    float4 a = *(const float4*)(s + i);
    float4 b = *(const float4*)(s + i + 4);
    __half2 h0 = __floats2half2_rn(a.x, a.y);
    __half2 h1 = __floats2half2_rn(a.z, a.w);
    __half2 h2 = __floats2half2_rn(b.x, b.y);
    __half2 h3 = __floats2half2_rn(b.z, b.w);
    uint4 o;
    o.x = *(uint32_t*)&h0; o.y = *(uint32_t*)&h1;
    o.z = *(uint32_t*)&h2; o.w = *(uint32_t*)&h3;
    *(uint4*)(d + i) = o;
}

// ---------------- GEMM1: hid = silu(X@W1) * (X@W3) ----------------
__global__ __launch_bounds__(256)
void gemm1_kernel() {
    extern __shared__ __half sm[];
    const int ex  = blockIdx.z;
    const int n_e = g_cnt[ex];
    const int m0  = blockIdx.x * BM;
    if (m0 >= n_e) return;
    const int n0  = blockIdx.y * BN;
    const int tid = threadIdx.x;
    const int wid = tid >> 5;
    const int wm  = wid & 1, wn = wid >> 1;

    const uint32_t smb = smem_u32(sm);

    // A loader: row ar = tid>>1, 4 contiguous 16B chunks at col (tid&1)*32 halves
    const int ar = tid >> 1, ac = (tid & 1) * 4;
    int rc = m0 + ar; if (rc > n_e - 1) rc = n_e - 1;
    const __half* asrc = g_xh + (size_t)g_tok[ex * TOK + rc] * HDIM + ac * 8;
    const uint32_t aoff = (ar * ALDH + ac * 8) * 2;

    // B loaders: k-row rb = tid>>2, 4 contiguous chunks at col (tid&3)*32 halves
    const int rb = tid >> 2, bc = (tid & 3) * 4;
    const __half* b1src = g_w1h + (size_t)ex * HDIM * FDIM + (size_t)rb * FDIM + n0 + bc * 8;
    const __half* b3src = g_w3h + (size_t)ex * HDIM * FDIM + (size_t)rb * FDIM + n0 + bc * 8;
    const uint32_t boff = (rb * BLDH + bc * 8) * 2;

    auto issue = [&](int c) {
        const uint32_t base = smb + (uint32_t)(c & 1) * (STG1H * 2);
        const int k0 = c * BK;
        const __half* sa = asrc + k0;
        const uint32_t ab = base + aoff;
#pragma unroll
        for (int u = 0; u < 4; u++) cpa(ab + u * 16, sa + u * 8);
        const __half* s1 = b1src + (size_t)k0 * FDIM;
        const __half* s3 = b3src + (size_t)k0 * FDIM;
        const uint32_t b1b = base + ASZH * 2 + boff;
        const uint32_t b3b = base + (ASZH + BSZH) * 2 + boff;
#pragma unroll
        for (int u = 0; u < 4; u++) cpa(b1b + u * 16, s1 + u * 8);
#pragma unroll
        for (int u = 0; u < 4; u++) cpa(b3b + u * 16, s3 + u * 8);
        cpcommit();
    };

    wmma::fragment<wmma::accumulator, 16, 16, 16, float> acc1[4][2], acc3[4][2];
#pragma unroll
    for (int i = 0; i < 4; i++)
#pragma unroll
        for (int j = 0; j < 2; j++) {
            wmma::fill_fragment(acc1[i][j], 0.f);
            wmma::fill_fragment(acc3[i][j], 0.f);
        }

    issue(0);
    for (int c = 0; c < NC1; c++) {
        cpwait<0>();
        __syncthreads();
        if (c + 1 < NC1) issue(c + 1);   // async; overlaps compute below

        const __half* As  = sm + (c & 1) * STG1H;
        const __half* B1s = As + ASZH;
        const __half* B3s = As + ASZH + BSZH;
#pragma unroll
        for (int kc = 0; kc < BK; kc += 16) {
            wmma::fragment<wmma::matrix_a, 16, 16, 16, __half, wmma::row_major> af[4];
            wmma::fragment<wmma::matrix_b, 16, 16, 16, __half, wmma::row_major> bf1[2], bf3[2];
#pragma unroll
            for (int i = 0; i < 4; i++)
                wmma::load_matrix_sync(af[i], As + (wm * 64 + i * 16) * ALDH + kc, ALDH);
#pragma unroll
            for (int j = 0; j < 2; j++) {
                wmma::load_matrix_sync(bf1[j], B1s + kc * BLDH + wn * 32 + j * 16, BLDH);
                wmma::load_matrix_sync(bf3[j], B3s + kc * BLDH + wn * 32 + j * 16, BLDH);
            }
#pragma unroll
            for (int i = 0; i < 4; i++)
#pragma unroll
                for (int j = 0; j < 2; j++) {
                    wmma::mma_sync(acc1[i][j], af[i], bf1[j], acc1[i][j]);
                    wmma::mma_sync(acc3[i][j], af[i], bf3[j], acc3[i][j]);
                }
        }
    }
    __syncthreads();   // protect smem reuse by epilogue

    // epilogue: silu(h1)*h3, two 64-row phases through smem, fp16 global store
    float* Cs = (float*)sm;   // 64 x CLD floats
    __half* hidb = g_hidh + (size_t)ex * TOK * FDIM;
#pragma unroll 1
    for (int p = 0; p < 2; p++) {
        if (wm == p) {
#pragma unroll
            for (int i = 0; i < 4; i++)
#pragma unroll
                for (int j = 0; j < 2; j++) {
#pragma unroll
                    for (int t = 0; t < acc1[i][j].num_elements; t++) {
                        float h1 = acc1[i][j].x[t];
                        float h3 = acc3[i][j].x[t];
                        acc1[i][j].x[t] = (h1 / (1.f + __expf(-h1))) * h3;
                    }
                    wmma::store_matrix_sync(Cs + (i * 16) * CLD + wn * 32 + j * 16,
                                            acc1[i][j], CLD, wmma::mem_row_major);
                }
        }
        __syncthreads();
#pragma unroll
        for (int it = 0; it < 4; it++) {
            int u = tid + 256 * it;                 // 1024 chunks: 64 rows x 16
            int r = u >> 4, c8 = u & 15;
            int grow = m0 + p * 64 + r;
            if (grow < n_e) {
                const float* src = Cs + r * CLD + c8 * 8;
                __half2 h0 = __floats2half2_rn(src[0], src[1]);
                __half2 h1 = __floats2half2_rn(src[2], src[3]);
                __half2 h2 = __floats2half2_rn(src[4], src[5]);
                __half2 h3 = __floats2half2_rn(src[6], src[7]);
                uint4 o;
                o.x = *(uint32_t*)&h0; o.y = *(uint32_t*)&h1;
                o.z = *(uint32_t*)&h2; o.w = *(uint32_t*)&h3;
                *(uint4*)(hidb + (size_t)grow * FDIM + n0 + c8 * 8) = o;
            }
        }
        __syncthreads();
    }
}

// ---------------- GEMM2: partial = (hid @ W2) * combine_wt, row-scattered ----------------
__global__ __launch_bounds__(256)
void gemm2_kernel() {
    extern __shared__ __half sm[];
    const int ex  = blockIdx.z;
    const int n_e = g_cnt[ex];
    const int m0  = blockIdx.x * BM;
    if (m0 >= n_e) return;
    const int n0  = blockIdx.y * BN;
    const int tid = threadIdx.x;
    const int wid = tid >> 5;
    const int wm  = wid & 1, wn = wid >> 1;

    const uint32_t smb = smem_u32(sm);

    const int ar = tid >> 1, ac = (tid & 1) * 4;
    const __half* asrc = g_hidh + ((size_t)ex * TOK + m0 + ar) * FDIM + ac * 8;
    const uint32_t aoff = (ar * ALDH + ac * 8) * 2;

    const int rb = tid >> 2, bc = (tid & 3) * 4;
    const __half* bsrc = g_w2h + (size_t)ex * FDIM * HDIM + (size_t)rb * HDIM + n0 + bc * 8;
    const uint32_t boff = (rb * BLDH + bc * 8) * 2;

    auto issue = [&](int c) {
        const uint32_t base = smb + (uint32_t)(c % 3) * (STG2H * 2);
        const int k0 = c * BK;
        const __half* sa = asrc + k0;
        const uint32_t ab = base + aoff;
#pragma unroll
        for (int u = 0; u < 4; u++) cpa(ab + u * 16, sa + u * 8);
        const __half* s2 = bsrc + (size_t)k0 * HDIM;
        const uint32_t bb = base + ASZH * 2 + boff;
#pragma unroll
        for (int u = 0; u < 4; u++) cpa(bb + u * 16, s2 + u * 8);
        cpcommit();
    };

    wmma::fragment<wmma::accumulator, 16, 16, 16, float> acc[4][2];
#pragma unroll
    for (int i = 0; i < 4; i++)
#pragma unroll
        for (int j = 0; j < 2; j++) wmma::fill_fragment(acc[i][j], 0.f);

    issue(0); issue(1);
    for (int c = 0; c < NC2; c++) {
        if (c + 2 < NC2) { cpwait<1>(); } else { cpwait<0>(); }
        __syncthreads();
        if (c + 2 < NC2) issue(c + 2);   // overwrites stage (c-1)%3: safe after barrier

        const __half* As = sm + (c % 3) * STG2H;
        const __half* Bs = As + ASZH;
#pragma unroll
        for (int kc = 0; kc < BK; kc += 16) {
            wmma::fragment<wmma::matrix_a, 16, 16, 16, __half, wmma::row_major> af[4];
            wmma::fragment<wmma::matrix_b, 16, 16, 16, __half, wmma::row_major> bf[2];
#pragma unroll
            for (int i = 0; i < 4; i++)
                wmma::load_matrix_sync(af[i], As + (wm * 64 + i * 16) * ALDH + kc, ALDH);
#pragma unroll
            for (int j = 0; j < 2; j++)
                wmma::load_matrix_sync(bf[j], Bs + kc * BLDH + wn * 32 + j * 16, BLDH);
#pragma unroll
            for (int i = 0; i < 4; i++)
#pragma unroll
                for (int j = 0; j < 2; j++)
                    wmma::mma_sync(acc[i][j], af[i], bf[j], acc[i][j]);
        }
    }
    __syncthreads();

    // epilogue: two 64-row phases; scale by combine weight, row-scatter to g_partial
    float* Cs = (float*)sm;
#pragma unroll 1
    for (int p = 0; p < 2; p++) {
        if (wm == p) {
#pragma unroll
            for (int i = 0; i < 4; i++)
#pragma unroll
                for (int j = 0; j < 2; j++)
                    wmma::store_matrix_sync(Cs + (i * 16) * CLD + wn * 32 + j * 16,
                                            acc[i][j], CLD, wmma::mem_row_major);
        }
        __syncthreads();
#pragma unroll
        for (int it = 0; it < 8; it++) {
            int u = tid + 256 * it;                 // 2048 float4: 64 rows x 32
            int r = u >> 5, c4 = u & 31;
            int grow = m0 + p * 64 + r;
            if (grow < n_e) {
                int   drow = g_dst[ex * TOK + grow];
                float w    = g_wt [ex * TOK + grow];
                const float* src = Cs + r * CLD + c4 * 4;
                float4 v;
                v.x = w * src[0]; v.y = w * src[1];
                v.z = w * src[2]; v.w = w * src[3];
                *(float4*)(g_partial + (size_t)drow * HDIM + n0 + c4 * 4) = v;
            }
        }
        __syncthreads();
    }
}

__global__ void combine_kernel(float* __restrict__ out) {
    const size_t i = (size_t)blockIdx.x * 256 + threadIdx.x;
    const int c = HDIM / 4;
    const size_t t = i / c;
    const size_t j = i % c;
    const float4* p = (const float4*)g_partial;
    float4 a = p[(t * 2 + 0) * c + j];
    float4 b = p[(t * 2 + 1) * c + j];
    float4 r;
    r.x = a.x + b.x; r.y = a.y + b.y; r.z = a.z + b.z; r.w = a.w + b.w;
    ((float4*)out)[i] = r;
}

// ---------------- launch ----------------
extern "C" void kernel_launch(void* const* d_in, const int* in_sizes, int n_in,
                              void* d_out, int out_size) {
    const float* x  = (const float*)d_in[0];
    const float* gw = (const float*)d_in[1];
    const float* w1 = (const float*)d_in[2];
    const float* w3 = (const float*)d_in[3];
    const float* w2 = (const float*)d_in[4];
    float* out = (float*)d_out;

    cudaFuncSetAttribute(gemm1_kernel, cudaFuncAttributeMaxDynamicSharedMemorySize, DYN1);
    cudaFuncSetAttribute(gemm2_kernel, cudaFuncAttributeMaxDynamicSharedMemorySize, DYN2);

    __half* xh;  cudaGetSymbolAddress((void**)&xh,  g_xh);
    __half* w1h; cudaGetSymbolAddress((void**)&w1h, g_w1h);
    __half* w3h; cudaGetSymbolAddress((void**)&w3h, g_w3h);
    __half* w2h; cudaGetSymbolAddress((void**)&w2h, g_w2h);

    zero_kernel<<<1, 32>>>();
    route_kernel<<<TOK, 256>>>(x, gw);

    const size_t wn8 = (size_t)NEXP * HDIM * FDIM / 8;
    f2h_kernel<<<(unsigned)((size_t)TOK * HDIM / 8 / 256), 256>>>(x, xh);
    f2h_kernel<<<(unsigned)(wn8 / 256), 256>>>(w1, w1h);
    f2h_kernel<<<(unsigned)(wn8 / 256), 256>>>(w3, w3h);
    f2h_kernel<<<(unsigned)(wn8 / 256), 256>>>(w2, w2h);

    dim3 g1(TOK / BM, FDIM / BN, NEXP);
    gemm1_kernel<<<g1, 256, DYN1>>>();

    dim3 g2(TOK / BM, HDIM / BN, NEXP);
    gemm2_kernel<<<g2, 256, DYN2>>>();

    combine_kernel<<<(TOK * HDIM / 4) / 256, 256>>>(out);
}

// round 10
// speedup vs baseline: 1.0991x; 1.0991x over previous
#include <cuda_runtime.h>
#include <cuda_fp16.h>
#include <mma.h>
#include <math.h>
#include <stdint.h>

using namespace nvcuda;

#define TOK  2048
#define HDIM 2048
#define FDIM 7168
#define NEXP 8
#define TOPK 2

#define BM 128
#define BK 32
#define NC1 (HDIM / BK)   // 64
#define NC2 (FDIM / BK)   // 224

// gemm1 tile: 128x128, 256 threads
#define BN1 128
// gemm2 tile: 128x256, 512 threads
#define BN2 256

#define ALDH 40            // A smem row stride (halves): 32 data + 8 pad
#define BLDH1 136          // gemm1 B stride: 128 + 8
#define BLDH2 264          // gemm2 B stride: 256 + 8
#define CLD1 136
#define CLD2 264

#define ASZH  (BM * ALDH)           // 5120 halves
#define BSZH1 (BK * BLDH1)          // 4352 halves
#define BSZH2 (BK * BLDH2)          // 8448 halves
#define STG1H (ASZH + 2 * BSZH1)    // 13824 halves = 27648 B
#define STG2H (ASZH + BSZH2)        // 13568 halves = 27136 B
#define DYN1 (4 * STG1H * 2)        // 110592 B (4-stage)
#define DYN2 (4 * STG2H * 2)        // 108544 B (4-stage)

// ---------------- scratch ----------------
__device__ int    g_cnt[NEXP];
__device__ int    g_tok[NEXP * TOK];
__device__ int    g_dst[NEXP * TOK];
__device__ float  g_wt [NEXP * TOK];
__device__ __half g_xh  [(size_t)TOK * HDIM];
__device__ __half g_w1h [(size_t)NEXP * HDIM * FDIM];
__device__ __half g_w3h [(size_t)NEXP * HDIM * FDIM];
__device__ __half g_w2h [(size_t)NEXP * FDIM * HDIM];
__device__ __half g_hidh[(size_t)NEXP * TOK * FDIM];
__device__ float  g_partial[(size_t)TOK * TOPK * HDIM];

// ---------------- helpers ----------------
__device__ __forceinline__ uint32_t smem_u32(const void* p) {
    uint32_t a;
    asm("{ .reg .u64 t; cvta.to.shared.u64 t, %1; cvt.u32.u64 %0, t; }" : "=r"(a) : "l"(p));
    return a;
}
__device__ __forceinline__ void cpa(uint32_t s, const void* g) {
    asm volatile("cp.async.cg.shared.global [%0], [%1], 16;" :: "r"(s), "l"(g));
}
__device__ __forceinline__ void cpcommit() { asm volatile("cp.async.commit_group;"); }
template <int N>
__device__ __forceinline__ void cpwait() { asm volatile("cp.async.wait_group %0;" :: "n"(N)); }

// ---------------- small kernels ----------------
__global__ void zero_kernel() {
    if (threadIdx.x < NEXP) g_cnt[threadIdx.x] = 0;
}

// fp32 gate: exact top-2 matches jax.lax.top_k (strict > keeps lowest index on ties)
__global__ void route_kernel(const float* __restrict__ x, const float* __restrict__ gw) {
    const int t   = blockIdx.x;
    const int tid = threadIdx.x;

    float acc[NEXP];
#pragma unroll
    for (int e = 0; e < NEXP; e++) acc[e] = 0.f;

    const float* xt = x + (size_t)t * HDIM;
    for (int h = tid; h < HDIM; h += 256) {
        float xv = xt[h];
#pragma unroll
        for (int e = 0; e < NEXP; e++) acc[e] += xv * gw[h * NEXP + e];
    }

    __shared__ float s[NEXP][256];
#pragma unroll
    for (int e = 0; e < NEXP; e++) s[e][tid] = acc[e];
    __syncthreads();
    for (int off = 128; off > 0; off >>= 1) {
        if (tid < off) {
#pragma unroll
            for (int e = 0; e < NEXP; e++) s[e][tid] += s[e][tid + off];
        }
        __syncthreads();
    }

    if (tid == 0) {
        float v[NEXP];
#pragma unroll
        for (int e = 0; e < NEXP; e++) v[e] = s[e][0];
        int i1 = 0;
#pragma unroll
        for (int e = 1; e < NEXP; e++) if (v[e] > v[i1]) i1 = e;
        int i2 = (i1 == 0) ? 1 : 0;
#pragma unroll
        for (int e = 0; e < NEXP; e++)
            if (e != i1 && v[e] > v[i2]) i2 = e;

        float m  = fmaxf(v[i1], v[i2]);
        float e1 = __expf(v[i1] - m);
        float e2 = __expf(v[i2] - m);
        float inv = 1.f / (e1 + e2);

        int s0 = atomicAdd(&g_cnt[i1], 1);
        g_tok[i1 * TOK + s0] = t;
        g_dst[i1 * TOK + s0] = t * TOPK + 0;
        g_wt [i1 * TOK + s0] = e1 * inv;
        int s1 = atomicAdd(&g_cnt[i2], 1);
        g_tok[i2 * TOK + s1] = t;
        g_dst[i2 * TOK + s1] = t * TOPK + 1;
        g_wt [i2 * TOK + s1] = e2 * inv;
    }
}

// fp32 -> fp16 (RN), 8 elems/thread
__global__ void f2h_kernel(const float* __restrict__ s, __half* __restrict__ d) {
    const size_t i = ((size_t)blockIdx.x * 256 + threadIdx.x) * 8;
    float4 a = *(const float4*)(s + i);
    float4 b = *(const float4*)(s + i + 4);
    __half2 h0 = __floats2half2_rn(a.x, a.y);
    __half2 h1 = __floats2half2_rn(a.z, a.w);
    __half2 h2 = __floats2half2_rn(b.x, b.y);
    __half2 h3 = __floats2half2_rn(b.z, b.w);
    uint4 o;
    o.x = *(uint32_t*)&h0; o.y = *(uint32_t*)&h1;
    o.z = *(uint32_t*)&h2; o.w = *(uint32_t*)&h3;
    *(uint4*)(d + i) = o;
}

// ---------------- GEMM1: hid = silu(X@W1) * (X@W3); 256 thr, 128x128, 4-stage ----------------
__global__ __launch_bounds__(256)
void gemm1_kernel() {
    extern __shared__ __half sm[];
    const int ex  = blockIdx.z;
    const int n_e = g_cnt[ex];
    const int m0  = blockIdx.x * BM;
    if (m0 >= n_e) return;
    const int n0  = blockIdx.y * BN1;
    const int tid = threadIdx.x;
    const int wid = tid >> 5;
    const int wm  = wid & 1, wn = wid >> 1;

    const uint32_t smb = smem_u32(sm);

    // A loader: 2 chunks (16B) per thread; row r = tid>>1
    const int ar = tid >> 1, acb = (tid & 1) * 2;
    int rc = m0 + ar; if (rc > n_e - 1) rc = n_e - 1;
    const __half* asrc = g_xh + (size_t)g_tok[ex * TOK + rc] * HDIM + acb * 8;
    const uint32_t aoff = (ar * ALDH + acb * 8) * 2;

    // B loaders: 2 chunks each for B1/B3; k-row rb = tid>>3
    const int rb = tid >> 3, bcb = (tid & 7) * 2;
    const __half* b1src = g_w1h + (size_t)ex * HDIM * FDIM + (size_t)rb * FDIM + n0 + bcb * 8;
    const __half* b3src = g_w3h + (size_t)ex * HDIM * FDIM + (size_t)rb * FDIM + n0 + bcb * 8;
    const uint32_t boff = (rb * BLDH1 + bcb * 8) * 2;

    auto issue = [&](int c) {
        const uint32_t base = smb + (uint32_t)(c & 3) * (STG1H * 2);
        const int k0 = c * BK;
        cpa(base + aoff,      asrc + k0);
        cpa(base + aoff + 16, asrc + k0 + 8);
        const __half* s1 = b1src + (size_t)k0 * FDIM;
        const __half* s3 = b3src + (size_t)k0 * FDIM;
        const uint32_t b1b = base + ASZH * 2 + boff;
        const uint32_t b3b = base + (ASZH + BSZH1) * 2 + boff;
        cpa(b1b, s1); cpa(b1b + 16, s1 + 8);
        cpa(b3b, s3); cpa(b3b + 16, s3 + 8);
        cpcommit();
    };

    wmma::fragment<wmma::accumulator, 16, 16, 16, float> acc1[4][2], acc3[4][2];
#pragma unroll
    for (int i = 0; i < 4; i++)
#pragma unroll
        for (int j = 0; j < 2; j++) {
            wmma::fill_fragment(acc1[i][j], 0.f);
            wmma::fill_fragment(acc3[i][j], 0.f);
        }

    issue(0); issue(1); issue(2);
    for (int c = 0; c < NC1; c++) {
        if (c + 3 < NC1) { issue(c + 3); cpwait<3>(); }
        else if (c + 2 < NC1) cpwait<2>();
        else if (c + 1 < NC1) cpwait<1>();
        else cpwait<0>();
        __syncthreads();

        const __half* As  = sm + (c & 3) * STG1H;
        const __half* B1s = As + ASZH;
        const __half* B3s = As + ASZH + BSZH1;
#pragma unroll
        for (int kc = 0; kc < BK; kc += 16) {
            wmma::fragment<wmma::matrix_a, 16, 16, 16, __half, wmma::row_major> af[4];
            wmma::fragment<wmma::matrix_b, 16, 16, 16, __half, wmma::row_major> bf1[2], bf3[2];
#pragma unroll
            for (int i = 0; i < 4; i++)
                wmma::load_matrix_sync(af[i], As + (wm * 64 + i * 16) * ALDH + kc, ALDH);
#pragma unroll
            for (int j = 0; j < 2; j++) {
                wmma::load_matrix_sync(bf1[j], B1s + kc * BLDH1 + wn * 32 + j * 16, BLDH1);
                wmma::load_matrix_sync(bf3[j], B3s + kc * BLDH1 + wn * 32 + j * 16, BLDH1);
            }
#pragma unroll
            for (int i = 0; i < 4; i++)
#pragma unroll
                for (int j = 0; j < 2; j++) {
                    wmma::mma_sync(acc1[i][j], af[i], bf1[j], acc1[i][j]);
                    wmma::mma_sync(acc3[i][j], af[i], bf3[j], acc3[i][j]);
                }
        }
        __syncthreads();
    }

    // epilogue: silu(h1)*h3, two 64-row phases through smem, fp16 global store
    float* Cs = (float*)sm;   // 64 x CLD1 floats
    __half* hidb = g_hidh + (size_t)ex * TOK * FDIM;
#pragma unroll 1
    for (int p = 0; p < 2; p++) {
        if (wm == p) {
#pragma unroll
            for (int i = 0; i < 4; i++)
#pragma unroll
                for (int j = 0; j < 2; j++) {
#pragma unroll
                    for (int t = 0; t < acc1[i][j].num_elements; t++) {
                        float h1 = acc1[i][j].x[t];
                        float h3 = acc3[i][j].x[t];
                        acc1[i][j].x[t] = (h1 / (1.f + __expf(-h1))) * h3;
                    }
                    wmma::store_matrix_sync(Cs + (i * 16) * CLD1 + wn * 32 + j * 16,
                                            acc1[i][j], CLD1, wmma::mem_row_major);
                }
        }
        __syncthreads();
#pragma unroll
        for (int it = 0; it < 4; it++) {
            int u = tid + 256 * it;                 // 1024 chunks: 64 rows x 16
            int r = u >> 4, c8 = u & 15;
            int grow = m0 + p * 64 + r;
            if (grow < n_e) {
                const float* src = Cs + r * CLD1 + c8 * 8;
                __half2 h0 = __floats2half2_rn(src[0], src[1]);
                __half2 h1 = __floats2half2_rn(src[2], src[3]);
                __half2 h2 = __floats2half2_rn(src[4], src[5]);
                __half2 h3 = __floats2half2_rn(src[6], src[7]);
                uint4 o;
                o.x = *(uint32_t*)&h0; o.y = *(uint32_t*)&h1;
                o.z = *(uint32_t*)&h2; o.w = *(uint32_t*)&h3;
                *(uint4*)(hidb + (size_t)grow * FDIM + n0 + c8 * 8) = o;
            }
        }
        __syncthreads();
    }
}

// ---------------- GEMM2: partial = (hid @ W2) * combine_wt; 512 thr, 128x256, 4-stage ----------------
__global__ __launch_bounds__(512)
void gemm2_kernel() {
    extern __shared__ __half sm[];
    const int ex  = blockIdx.z;
    const int n_e = g_cnt[ex];
    const int m0  = blockIdx.x * BM;
    if (m0 >= n_e) return;
    const int n0  = blockIdx.y * BN2;
    const int tid = threadIdx.x;
    const int wid = tid >> 5;                 // 0..15
    const int wm  = wid & 1, wn = wid >> 1;   // warp tile: rows wm*64, cols wn*32

    const uint32_t smb = smem_u32(sm);

    // A loader: 1 chunk per thread (128 rows x 4 chunks = 512)
    const int ar = tid >> 2, ac = tid & 3;
    int rc = m0 + ar; if (rc > n_e - 1) rc = n_e - 1;
    const __half* asrc = g_hidh + ((size_t)ex * TOK + rc) * FDIM + ac * 8;
    const uint32_t aoff = (ar * ALDH + ac * 8) * 2;

    // B loader: 2 chunks per thread (32 k-rows x 32 chunks = 1024)
    const int rb = tid >> 4, bc2 = (tid & 15) * 2;
    const __half* bsrc = g_w2h + (size_t)ex * FDIM * HDIM + (size_t)rb * HDIM + n0 + bc2 * 8;
    const uint32_t boff = (rb * BLDH2 + bc2 * 8) * 2;

    auto issue = [&](int c) {
        const uint32_t base = smb + (uint32_t)(c & 3) * (STG2H * 2);
        const int k0 = c * BK;
        cpa(base + aoff, asrc + k0);
        const __half* s2 = bsrc + (size_t)k0 * HDIM;
        const uint32_t bb = base + ASZH * 2 + boff;
        cpa(bb, s2); cpa(bb + 16, s2 + 8);
        cpcommit();
    };

    wmma::fragment<wmma::accumulator, 16, 16, 16, float> acc[4][2];
#pragma unroll
    for (int i = 0; i < 4; i++)
#pragma unroll
        for (int j = 0; j < 2; j++) wmma::fill_fragment(acc[i][j], 0.f);

    issue(0); issue(1); issue(2);
    for (int c = 0; c < NC2; c++) {
        if (c + 3 < NC2) { issue(c + 3); cpwait<3>(); }
        else if (c + 2 < NC2) cpwait<2>();
        else if (c + 1 < NC2) cpwait<1>();
        else cpwait<0>();
        __syncthreads();

        const __half* As = sm + (c & 3) * STG2H;
        const __half* Bs = As + ASZH;
#pragma unroll
        for (int kc = 0; kc < BK; kc += 16) {
            wmma::fragment<wmma::matrix_a, 16, 16, 16, __half, wmma::row_major> af[4];
            wmma::fragment<wmma::matrix_b, 16, 16, 16, __half, wmma::row_major> bf[2];
#pragma unroll
            for (int i = 0; i < 4; i++)
                wmma::load_matrix_sync(af[i], As + (wm * 64 + i * 16) * ALDH + kc, ALDH);
#pragma unroll
            for (int j = 0; j < 2; j++)
                wmma::load_matrix_sync(bf[j], Bs + kc * BLDH2 + wn * 32 + j * 16, BLDH2);
#pragma unroll
            for (int i = 0; i < 4; i++)
#pragma unroll
                for (int j = 0; j < 2; j++)
                    wmma::mma_sync(acc[i][j], af[i], bf[j], acc[i][j]);
        }
        __syncthreads();
    }

    // epilogue: two 64-row phases; scale by combine weight, row-scatter to g_partial
    float* Cs = (float*)sm;   // 64 x CLD2 floats = 67584 B
#pragma unroll 1
    for (int p = 0; p < 2; p++) {
        if (wm == p) {
#pragma unroll
            for (int i = 0; i < 4; i++)
#pragma unroll
                for (int j = 0; j < 2; j++)
                    wmma::store_matrix_sync(Cs + (i * 16) * CLD2 + wn * 32 + j * 16,
                                            acc[i][j], CLD2, wmma::mem_row_major);
        }
        __syncthreads();
#pragma unroll
        for (int it = 0; it < 8; it++) {
            int u = tid + 512 * it;                 // 4096 float4: 64 rows x 64
            int r = u >> 6, c4 = u & 63;
            int grow = m0 + p * 64 + r;
            if (grow < n_e) {
                int   drow = g_dst[ex * TOK + grow];
                float w    = g_wt [ex * TOK + grow];
                const float* src = Cs + r * CLD2 + c4 * 4;
                float4 v;
                v.x = w * src[0]; v.y = w * src[1];
                v.z = w * src[2]; v.w = w * src[3];
                *(float4*)(g_partial + (size_t)drow * HDIM + n0 + c4 * 4) = v;
            }
        }
        __syncthreads();
    }
}

__global__ void combine_kernel(float* __restrict__ out) {
    const size_t i = (size_t)blockIdx.x * 256 + threadIdx.x;
    const int c = HDIM / 4;
    const size_t t = i / c;
    const size_t j = i % c;
    const float4* p = (const float4*)g_partial;
    float4 a = p[(t * 2 + 0) * c + j];
    float4 b = p[(t * 2 + 1) * c + j];
    float4 r;
    r.x = a.x + b.x; r.y = a.y + b.y; r.z = a.z + b.z; r.w = a.w + b.w;
    ((float4*)out)[i] = r;
}

// ---------------- launch ----------------
extern "C" void kernel_launch(void* const* d_in, const int* in_sizes, int n_in,
                              void* d_out, int out_size) {
    const float* x  = (const float*)d_in[0];
    const float* gw = (const float*)d_in[1];
    const float* w1 = (const float*)d_in[2];
    const float* w3 = (const float*)d_in[3];
    const float* w2 = (const float*)d_in[4];
    float* out = (float*)d_out;

    cudaFuncSetAttribute(gemm1_kernel, cudaFuncAttributeMaxDynamicSharedMemorySize, DYN1);
    cudaFuncSetAttribute(gemm2_kernel, cudaFuncAttributeMaxDynamicSharedMemorySize, DYN2);

    __half* xh;  cudaGetSymbolAddress((void**)&xh,  g_xh);
    __half* w1h; cudaGetSymbolAddress((void**)&w1h, g_w1h);
    __half* w3h; cudaGetSymbolAddress((void**)&w3h, g_w3h);
    __half* w2h; cudaGetSymbolAddress((void**)&w2h, g_w2h);

    zero_kernel<<<1, 32>>>();
    route_kernel<<<TOK, 256>>>(x, gw);

    const size_t wn8 = (size_t)NEXP * HDIM * FDIM / 8;
    f2h_kernel<<<(unsigned)((size_t)TOK * HDIM / 8 / 256), 256>>>(x, xh);
    f2h_kernel<<<(unsigned)(wn8 / 256), 256>>>(w1, w1h);
    f2h_kernel<<<(unsigned)(wn8 / 256), 256>>>(w3, w3h);
    f2h_kernel<<<(unsigned)(wn8 / 256), 256>>>(w2, w2h);

    dim3 g1(TOK / BM, FDIM / BN1, NEXP);
    gemm1_kernel<<<g1, 256, DYN1>>>();

    dim3 g2(TOK / BM, HDIM / BN2, NEXP);
    gemm2_kernel<<<g2, 512, DYN2>>>();

    combine_kernel<<<(TOK * HDIM / 4) / 256, 256>>>(out);
}

// round 13
// speedup vs baseline: 1.1426x; 1.0396x over previous
#include <cuda_runtime.h>
#include <cuda_fp16.h>
#include <mma.h>
#include <math.h>
#include <stdint.h>

using namespace nvcuda;

#define TOK  2048
#define HDIM 2048
#define FDIM 7168
#define NEXP 8
#define TOPK 2

#define BM 128
#define BK 32
#define NC1 (HDIM / BK)   // 64
#define NC2 (FDIM / BK)   // 224

#define BN1 128
#define BN2 256
#define NB1 (FDIM / BN1)  // 56 gemm1 N-tiles
#define W2SL 7            // extra blockIdx.y slices in gemm1 grid for w2 conversion

#define ALDH 40
#define BLDH1 136
#define BLDH2 264
#define CLD1 136
#define CLD2 264

#define ASZH  (BM * ALDH)           // 5120 halves
#define BSZH1 (BK * BLDH1)          // 4352 halves
#define BSZH2 (BK * BLDH2)          // 8448 halves
#define STG1H (ASZH + 2 * BSZH1)    // 13824 halves
#define STG2H (ASZH + BSZH2)        // 13568 halves
#define DYN1 (4 * STG1H * 2)        // 110592 B
#define DYN2 (4 * STG2H * 2)        // 108544 B

// ---------------- scratch ----------------
__device__ int    g_cnt[NEXP];
__device__ int    g_tok[NEXP * TOK];
__device__ int    g_dst[NEXP * TOK];
__device__ float  g_wt [NEXP * TOK];
__device__ __half g_xh  [(size_t)TOK * HDIM];
__device__ __half g_w1h [(size_t)NEXP * HDIM * FDIM];
__device__ __half g_w3h [(size_t)NEXP * HDIM * FDIM];
__device__ __half g_w2h [(size_t)NEXP * FDIM * HDIM];
__device__ __half g_hidh[(size_t)NEXP * TOK * FDIM];
__device__ float  g_partial[(size_t)TOK * TOPK * HDIM];

// ---------------- helpers ----------------
__device__ __forceinline__ uint32_t smem_u32(const void* p) {
    uint32_t a;
    asm("{ .reg .u64 t; cvta.to.shared.u64 t, %1; cvt.u32.u64 %0, t; }" : "=r"(a) : "l"(p));
    return a;
}
__device__ __forceinline__ void cpa(uint32_t s, const void* g) {
    asm volatile("cp.async.cg.shared.global [%0], [%1], 16;" :: "r"(s), "l"(g));
}
__device__ __forceinline__ void cpcommit() { asm volatile("cp.async.commit_group;"); }
template <int N>
__device__ __forceinline__ void cpwait() { asm volatile("cp.async.wait_group %0;" :: "n"(N)); }

__device__ __forceinline__ void f2h_chunk(const float* __restrict__ s,
                                          __half* __restrict__ d, size_t i) {
    float4 a = *(const float4*)(s + i);
    float4 b = *(const float4*)(s + i + 4);
    __half2 h0 = __floats2half2_rn(a.x, a.y);
    __half2 h1 = __floats2half2_rn(a.z, a.w);
    __half2 h2 = __floats2half2_rn(b.x, b.y);
    __half2 h3 = __floats2half2_rn(b.z, b.w);
    uint4 o;
    o.x = *(uint32_t*)&h0; o.y = *(uint32_t*)&h1;
    o.z = *(uint32_t*)&h2; o.w = *(uint32_t*)&h3;
    *(uint4*)(d + i) = o;
}

// ---------------- prep: route + f2h(x) + f2h(w1) + f2h(w3), one fused grid ----------------
// grid.x = 2048 (route) + 2048 (x) + 57344 (w1) + 57344 (w3) = 118784, 256 threads
__global__ void prep_kernel(const float* __restrict__ x, const float* __restrict__ gw,
                            const float* __restrict__ w1, const float* __restrict__ w3,
                            __half* __restrict__ xh, __half* __restrict__ w1h,
                            __half* __restrict__ w3h) {
    const int bid = blockIdx.x;
    const int tid = threadIdx.x;

    if (bid >= 2048) {
        // conversion blocks: 8 fp32->fp16 elems per thread
        int cb = bid - 2048;
        if (cb < 2048) {
            f2h_chunk(x, xh, ((size_t)cb * 256 + tid) * 8);
        } else if (cb < 2048 + 57344) {
            f2h_chunk(w1, w1h, ((size_t)(cb - 2048) * 256 + tid) * 8);
        } else {
            f2h_chunk(w3, w3h, ((size_t)(cb - 2048 - 57344) * 256 + tid) * 8);
        }
        return;
    }

    // ---- routing: fp32 gate, exact top-2 (strict > keeps lowest index on ties) ----
    const int t = bid;
    float acc[NEXP];
#pragma unroll
    for (int e = 0; e < NEXP; e++) acc[e] = 0.f;

    const float* xt = x + (size_t)t * HDIM;
    for (int h = tid; h < HDIM; h += 256) {
        float xv = xt[h];
#pragma unroll
        for (int e = 0; e < NEXP; e++) acc[e] += xv * gw[h * NEXP + e];
    }

    __shared__ float s[NEXP][256];
#pragma unroll
    for (int e = 0; e < NEXP; e++) s[e][tid] = acc[e];
    __syncthreads();
    for (int off = 128; off > 0; off >>= 1) {
        if (tid < off) {
#pragma unroll
            for (int e = 0; e < NEXP; e++) s[e][tid] += s[e][tid + off];
        }
        __syncthreads();
    }

    if (tid == 0) {
        float v[NEXP];
#pragma unroll
        for (int e = 0; e < NEXP; e++) v[e] = s[e][0];
        int i1 = 0;
#pragma unroll
        for (int e = 1; e < NEXP; e++) if (v[e] > v[i1]) i1 = e;
        int i2 = (i1 == 0) ? 1 : 0;
#pragma unroll
        for (int e = 0; e < NEXP; e++)
            if (e != i1 && v[e] > v[i2]) i2 = e;

        float m  = fmaxf(v[i1], v[i2]);
        float e1 = __expf(v[i1] - m);
        float e2 = __expf(v[i2] - m);
        float inv = 1.f / (e1 + e2);

        int s0 = atomicAdd(&g_cnt[i1], 1);
        g_tok[i1 * TOK + s0] = t;
        g_dst[i1 * TOK + s0] = t * TOPK + 0;
        g_wt [i1 * TOK + s0] = e1 * inv;
        int s1 = atomicAdd(&g_cnt[i2], 1);
        g_tok[i2 * TOK + s1] = t;
        g_dst[i2 * TOK + s1] = t * TOPK + 1;
        g_wt [i2 * TOK + s1] = e2 * inv;
    }
}

// ---------------- GEMM1 (+ fused f2h(w2) on extra y-slices) ----------------
// grid = (16, NB1 + W2SL, 8); y >= NB1 -> w2 conversion block
__global__ __launch_bounds__(256)
void gemm1_kernel(const float* __restrict__ w2, __half* __restrict__ w2h) {
    extern __shared__ __half sm[];

    if (blockIdx.y >= NB1) {
        // f2h(w2): 896 blocks x 64 iters x 2048 halves = 117,440,512 = NEXP*FDIM*HDIM
        const int fid = (blockIdx.z * W2SL + (blockIdx.y - NB1)) * 16 + blockIdx.x;
        const size_t base = (size_t)fid * 131072;
#pragma unroll 4
        for (int it = 0; it < 64; it++)
            f2h_chunk(w2, w2h, base + (size_t)it * 2048 + threadIdx.x * 8);
        return;
    }

    const int ex  = blockIdx.z;
    const int n_e = g_cnt[ex];
    const int m0  = blockIdx.x * BM;
    if (m0 >= n_e) return;
    const int n0  = blockIdx.y * BN1;
    const int tid = threadIdx.x;
    const int wid = tid >> 5;
    const int wm  = wid & 1, wn = wid >> 1;

    const uint32_t smb = smem_u32(sm);

    const int ar = tid >> 1, acb = (tid & 1) * 2;
    int rc = m0 + ar; if (rc > n_e - 1) rc = n_e - 1;
    const __half* asrc = g_xh + (size_t)g_tok[ex * TOK + rc] * HDIM + acb * 8;
    const uint32_t aoff = (ar * ALDH + acb * 8) * 2;

    const int rb = tid >> 3, bcb = (tid & 7) * 2;
    const __half* b1src = g_w1h + (size_t)ex * HDIM * FDIM + (size_t)rb * FDIM + n0 + bcb * 8;
    const __half* b3src = g_w3h + (size_t)ex * HDIM * FDIM + (size_t)rb * FDIM + n0 + bcb * 8;
    const uint32_t boff = (rb * BLDH1 + bcb * 8) * 2;

    auto issue = [&](int c) {
        const uint32_t base = smb + (uint32_t)(c & 3) * (STG1H * 2);
        const int k0 = c * BK;
        cpa(base + aoff,      asrc + k0);
        cpa(base + aoff + 16, asrc + k0 + 8);
        const __half* s1 = b1src + (size_t)k0 * FDIM;
        const __half* s3 = b3src + (size_t)k0 * FDIM;
        const uint32_t b1b = base + ASZH * 2 + boff;
        const uint32_t b3b = base + (ASZH + BSZH1) * 2 + boff;
        cpa(b1b, s1); cpa(b1b + 16, s1 + 8);
        cpa(b3b, s3); cpa(b3b + 16, s3 + 8);
        cpcommit();
    };

    wmma::fragment<wmma::accumulator, 16, 16, 16, float> acc1[4][2], acc3[4][2];
#pragma unroll
    for (int i = 0; i < 4; i++)
#pragma unroll
        for (int j = 0; j < 2; j++) {
            wmma::fill_fragment(acc1[i][j], 0.f);
            wmma::fill_fragment(acc3[i][j], 0.f);
        }

    issue(0); issue(1); issue(2);
    for (int c = 0; c < NC1; c++) {
        if (c + 2 < NC1) cpwait<2>();
        else if (c + 1 < NC1) cpwait<1>();
        else cpwait<0>();
        __syncthreads();
        if (c + 3 < NC1) issue(c + 3);   // writes stage (c-1)&3, consumed at iter c-1

        const __half* As  = sm + (c & 3) * STG1H;
        const __half* B1s = As + ASZH;
        const __half* B3s = As + ASZH + BSZH1;
#pragma unroll
        for (int kc = 0; kc < BK; kc += 16) {
            wmma::fragment<wmma::matrix_a, 16, 16, 16, __half, wmma::row_major> af[4];
            wmma::fragment<wmma::matrix_b, 16, 16, 16, __half, wmma::row_major> bf1[2], bf3[2];
#pragma unroll
            for (int i = 0; i < 4; i++)
                wmma::load_matrix_sync(af[i], As + (wm * 64 + i * 16) * ALDH + kc, ALDH);
#pragma unroll
            for (int j = 0; j < 2; j++) {
                wmma::load_matrix_sync(bf1[j], B1s + kc * BLDH1 + wn * 32 + j * 16, BLDH1);
                wmma::load_matrix_sync(bf3[j], B3s + kc * BLDH1 + wn * 32 + j * 16, BLDH1);
            }
#pragma unroll
            for (int i = 0; i < 4; i++)
#pragma unroll
                for (int j = 0; j < 2; j++) {
                    wmma::mma_sync(acc1[i][j], af[i], bf1[j], acc1[i][j]);
                    wmma::mma_sync(acc3[i][j], af[i], bf3[j], acc3[i][j]);
                }
        }
    }
    __syncthreads();

    // epilogue: silu(h1)*h3, two 64-row phases through smem, fp16 global store
    float* Cs = (float*)sm;
    __half* hidb = g_hidh + (size_t)ex * TOK * FDIM;
#pragma unroll 1
    for (int p = 0; p < 2; p++) {
        if (wm == p) {
#pragma unroll
            for (int i = 0; i < 4; i++)
#pragma unroll
                for (int j = 0; j < 2; j++) {
#pragma unroll
                    for (int t = 0; t < acc1[i][j].num_elements; t++) {
                        float h1 = acc1[i][j].x[t];
                        float h3 = acc3[i][j].x[t];
                        acc1[i][j].x[t] = (h1 / (1.f + __expf(-h1))) * h3;
                    }
                    wmma::store_matrix_sync(Cs + (i * 16) * CLD1 + wn * 32 + j * 16,
                                            acc1[i][j], CLD1, wmma::mem_row_major);
                }
        }
        __syncthreads();
#pragma unroll
        for (int it = 0; it < 4; it++) {
            int u = tid + 256 * it;
            int r = u >> 4, c8 = u & 15;
            int grow = m0 + p * 64 + r;
            if (grow < n_e) {
                const float* src = Cs + r * CLD1 + c8 * 8;
                __half2 h0 = __floats2half2_rn(src[0], src[1]);
                __half2 h1 = __floats2half2_rn(src[2], src[3]);
                __half2 h2 = __floats2half2_rn(src[4], src[5]);
                __half2 h3 = __floats2half2_rn(src[6], src[7]);
                uint4 o;
                o.x = *(uint32_t*)&h0; o.y = *(uint32_t*)&h1;
                o.z = *(uint32_t*)&h2; o.w = *(uint32_t*)&h3;
                *(uint4*)(hidb + (size_t)grow * FDIM + n0 + c8 * 8) = o;
            }
        }
        __syncthreads();
    }
}

// ---------------- GEMM2: partial = (hid @ W2) * combine_wt; 512 thr, 128x256 ----------------
__global__ __launch_bounds__(512)
void gemm2_kernel() {
    extern __shared__ __half sm[];
    const int ex  = blockIdx.z;
    const int n_e = g_cnt[ex];
    const int m0  = blockIdx.x * BM;
    if (m0 >= n_e) return;
    const int n0  = blockIdx.y * BN2;
    const int tid = threadIdx.x;
    const int wid = tid >> 5;
    const int wm  = wid & 1, wn = wid >> 1;

    const uint32_t smb = smem_u32(sm);

    const int ar = tid >> 2, ac = tid & 3;
    int rc = m0 + ar; if (rc > n_e - 1) rc = n_e - 1;
    const __half* asrc = g_hidh + ((size_t)ex * TOK + rc) * FDIM + ac * 8;
    const uint32_t aoff = (ar * ALDH + ac * 8) * 2;

    const int rb = tid >> 4, bc2 = (tid & 15) * 2;
    const __half* bsrc = g_w2h + (size_t)ex * FDIM * HDIM + (size_t)rb * HDIM + n0 + bc2 * 8;
    const uint32_t boff = (rb * BLDH2 + bc2 * 8) * 2;

    auto issue = [&](int c) {
        const uint32_t base = smb + (uint32_t)(c & 3) * (STG2H * 2);
        const int k0 = c * BK;
        cpa(base + aoff, asrc + k0);
        const __half* s2 = bsrc + (size_t)k0 * HDIM;
        const uint32_t bb = base + ASZH * 2 + boff;
        cpa(bb, s2); cpa(bb + 16, s2 + 8);
        cpcommit();
    };

    wmma::fragment<wmma::accumulator, 16, 16, 16, float> acc[4][2];
#pragma unroll
    for (int i = 0; i < 4; i++)
#pragma unroll
        for (int j = 0; j < 2; j++) wmma::fill_fragment(acc[i][j], 0.f);

    issue(0); issue(1); issue(2);
    for (int c = 0; c < NC2; c++) {
        if (c + 2 < NC2) cpwait<2>();
        else if (c + 1 < NC2) cpwait<1>();
        else cpwait<0>();
        __syncthreads();
        if (c + 3 < NC2) issue(c + 3);

        const __half* As = sm + (c & 3) * STG2H;
        const __half* Bs = As + ASZH;
#pragma unroll
        for (int kc = 0; kc < BK; kc += 16) {
            wmma::fragment<wmma::matrix_a, 16, 16, 16, __half, wmma::row_major> af[4];
            wmma::fragment<wmma::matrix_b, 16, 16, 16, __half, wmma::row_major> bf[2];
#pragma unroll
            for (int i = 0; i < 4; i++)
                wmma::load_matrix_sync(af[i], As + (wm * 64 + i * 16) * ALDH + kc, ALDH);
#pragma unroll
            for (int j = 0; j < 2; j++)
                wmma::load_matrix_sync(bf[j], Bs + kc * BLDH2 + wn * 32 + j * 16, BLDH2);
#pragma unroll
            for (int i = 0; i < 4; i++)
#pragma unroll
                for (int j = 0; j < 2; j++)
                    wmma::mma_sync(acc[i][j], af[i], bf[j], acc[i][j]);
        }
    }
    __syncthreads();

    float* Cs = (float*)sm;
#pragma unroll 1
    for (int p = 0; p < 2; p++) {
        if (wm == p) {
#pragma unroll
            for (int i = 0; i < 4; i++)
#pragma unroll
                for (int j = 0; j < 2; j++)
                    wmma::store_matrix_sync(Cs + (i * 16) * CLD2 + wn * 32 + j * 16,
                                            acc[i][j], CLD2, wmma::mem_row_major);
        }
        __syncthreads();
#pragma unroll
        for (int it = 0; it < 8; it++) {
            int u = tid + 512 * it;
            int r = u >> 6, c4 = u & 63;
            int grow = m0 + p * 64 + r;
            if (grow < n_e) {
                int   drow = g_dst[ex * TOK + grow];
                float w    = g_wt [ex * TOK + grow];
                const float* src = Cs + r * CLD2 + c4 * 4;
                float4 v;
                v.x = w * src[0]; v.y = w * src[1];
                v.z = w * src[2]; v.w = w * src[3];
                *(float4*)(g_partial + (size_t)drow * HDIM + n0 + c4 * 4) = v;
            }
        }
        __syncthreads();
    }
}

__global__ void combine_kernel(float* __restrict__ out) {
    const size_t i = (size_t)blockIdx.x * 256 + threadIdx.x;
    const int c = HDIM / 4;
    const size_t t = i / c;
    const size_t j = i % c;
    const float4* p = (const float4*)g_partial;
    float4 a = p[(t * 2 + 0) * c + j];
    float4 b = p[(t * 2 + 1) * c + j];
    float4 r;
    r.x = a.x + b.x; r.y = a.y + b.y; r.z = a.z + b.z; r.w = a.w + b.w;
    ((float4*)out)[i] = r;
}

// ---------------- launch ----------------
extern "C" void kernel_launch(void* const* d_in, const int* in_sizes, int n_in,
                              void* d_out, int out_size) {
    const float* x  = (const float*)d_in[0];
    const float* gw = (const float*)d_in[1];
    const float* w1 = (const float*)d_in[2];
    const float* w3 = (const float*)d_in[3];
    const float* w2 = (const float*)d_in[4];
    float* out = (float*)d_out;

    cudaFuncSetAttribute(gemm1_kernel, cudaFuncAttributeMaxDynamicSharedMemorySize, DYN1);
    cudaFuncSetAttribute(gemm2_kernel, cudaFuncAttributeMaxDynamicSharedMemorySize, DYN2);

    __half* xh;  cudaGetSymbolAddress((void**)&xh,  g_xh);
    __half* w1h; cudaGetSymbolAddress((void**)&w1h, g_w1h);
    __half* w3h; cudaGetSymbolAddress((void**)&w3h, g_w3h);
    __half* w2h; cudaGetSymbolAddress((void**)&w2h, g_w2h);
    int* cnt;    cudaGetSymbolAddress((void**)&cnt, g_cnt);

    cudaMemsetAsync(cnt, 0, NEXP * sizeof(int));

    // fused prep: route (2048) + f2h x (2048) + f2h w1 (57344) + f2h w3 (57344)
    prep_kernel<<<118784, 256>>>(x, gw, w1, w3, xh, w1h, w3h);

    // gemm1 with fused f2h(w2) slices
    dim3 g1(TOK / BM, NB1 + W2SL, NEXP);
    gemm1_kernel<<<g1, 256, DYN1>>>(w2, w2h);

    dim3 g2(TOK / BM, HDIM / BN2, NEXP);
    gemm2_kernel<<<g2, 512, DYN2>>>();

    combine_kernel<<<(TOK * HDIM / 4) / 256, 256>>>(out);
}